// round 14
// baseline (speedup 1.0000x reference)
#include <cuda_runtime.h>
#include <math.h>

// Shapes (fixed):
//   x  : [B=8, C=128, D=4, H=128, W=128] -> 67,108,864 fp32 (256 MB)
//   w1, w2 : [C, C] row-major (w[o,c] = w[o*128 + c]); b1, b2 : [C]
// out = x * sigmoid(W2 @ relu(W1 @ max_{dhw}(x) + b1) + b2), gate per (b,c).

#define BC 1024              // B*C slices
#define SLICE4 16384         // 65536 floats / 4 per (b,c)

__device__ float d_gp[BC];    // per-(b,c) global max
__device__ float d_gate[BC];  // per-(b,c) sigmoid gate

// ---------------- Kernel 1: per-slice max reduce (proven 42.2us shape) ----------
__global__ __launch_bounds__(256) void max_reduce_kernel(const float4* __restrict__ x4) {
    const int bc = blockIdx.x;
    const float4* base = x4 + (size_t)bc * SLICE4;
    const int t = threadIdx.x;

    float m0 = -INFINITY, m1 = -INFINITY, m2 = -INFINITY, m3 = -INFINITY;
    #pragma unroll
    for (int i = 0; i < 16; i++) {
        float4 a = base[t + (4 * i + 0) * 256];
        float4 b = base[t + (4 * i + 1) * 256];
        float4 c = base[t + (4 * i + 2) * 256];
        float4 d = base[t + (4 * i + 3) * 256];
        m0 = fmaxf(m0, fmaxf(fmaxf(a.x, a.y), fmaxf(a.z, a.w)));
        m1 = fmaxf(m1, fmaxf(fmaxf(b.x, b.y), fmaxf(b.z, b.w)));
        m2 = fmaxf(m2, fmaxf(fmaxf(c.x, c.y), fmaxf(c.z, c.w)));
        m3 = fmaxf(m3, fmaxf(fmaxf(d.x, d.y), fmaxf(d.z, d.w)));
    }
    float m = fmaxf(fmaxf(m0, m1), fmaxf(m2, m3));

    #pragma unroll
    for (int off = 16; off > 0; off >>= 1)
        m = fmaxf(m, __shfl_xor_sync(0xFFFFFFFFu, m, off));

    __shared__ float s[8];
    if ((t & 31) == 0) s[t >> 5] = m;
    __syncthreads();
    if (t == 0) {
        float r = s[0];
        #pragma unroll
        for (int w = 1; w < 8; w++) r = fmaxf(r, s[w]);
        d_gp[bc] = r;
    }
    cudaTriggerProgrammaticLaunchCompletion();
}

// ---------------- Kernel 2: lean MLP gate (PDL secondary) ----------------
// Grid=8 (block per batch), 256 threads = 8 warps; warp w owns channels
// w*16..w*16+15; one float4/lane covers a 128-float weight row; shuffle-reduce.
__global__ __launch_bounds__(256) void mlp_gate_kernel(const float* __restrict__ w1,
                                                       const float* __restrict__ b1,
                                                       const float* __restrict__ w2,
                                                       const float* __restrict__ b2) {
    cudaGridDependencySynchronize();   // wait for reduce grid; its writes visible

    __shared__ float s_gp[128];
    __shared__ float s_h[128];
    const int b = blockIdx.x;
    const int t = threadIdx.x;
    const int wid = t >> 5, lane = t & 31;

    if (t < 128) s_gp[t] = d_gp[b * 128 + t];
    __syncthreads();

    // layer 1
    {
        float4 gv = ((const float4*)s_gp)[lane];
        #pragma unroll
        for (int k = 0; k < 16; k++) {
            const int c = wid * 16 + k;
            float4 wv = ((const float4*)(w1 + c * 128))[lane];
            float p = fmaf(gv.x, wv.x, fmaf(gv.y, wv.y, fmaf(gv.z, wv.z, gv.w * wv.w)));
            #pragma unroll
            for (int off = 16; off > 0; off >>= 1)
                p += __shfl_xor_sync(0xFFFFFFFFu, p, off);
            if (lane == 0) s_h[c] = fmaxf(p + b1[c], 0.0f);
        }
    }
    __syncthreads();

    // layer 2
    {
        float4 hv = ((const float4*)s_h)[lane];
        #pragma unroll
        for (int k = 0; k < 16; k++) {
            const int c = wid * 16 + k;
            float4 wv = ((const float4*)(w2 + c * 128))[lane];
            float p = fmaf(hv.x, wv.x, fmaf(hv.y, wv.y, fmaf(hv.z, wv.z, hv.w * wv.w)));
            #pragma unroll
            for (int off = 16; off > 0; off >>= 1)
                p += __shfl_xor_sync(0xFFFFFFFFu, p, off);
            if (lane == 0) {
                float z = p + b2[c];
                d_gate[b * 128 + c] = 1.0f / (1.0f + __expf(-z));
            }
        }
    }
    cudaTriggerProgrammaticLaunchCompletion();
}

// ---------------- Kernel 3: scale (PDL secondary, prefetch-before-sync) --------
// Grid=2048, reverse order; 256 threads x 32 float4. The first 4 float4 are
// gate-INDEPENDENT addresses, so prefetch them BEFORE the dependency sync:
// this kernel's first DRAM reads overlap the mlp/reduce tail.
__global__ __launch_bounds__(256) void scale_kernel(const float4* __restrict__ x4,
                                                    float4* __restrict__ o4) {
    const int blk = (2 * BC - 1) - blockIdx.x;
    const int bc = blk >> 1;
    const size_t off = (size_t)blk * (SLICE4 / 2);
    const float4* src = x4 + off;
    float4* dst = o4 + off;
    const int t = threadIdx.x;

    float4 p[4];
    #pragma unroll
    for (int i = 0; i < 4; i++) p[i] = src[t + i * 256];   // overlap with upstream

    cudaGridDependencySynchronize();   // gates now valid
    const float g = d_gate[bc];

    #pragma unroll
    for (int i = 0; i < 4; i++) {
        float4 v = p[i];
        v.x *= g; v.y *= g; v.z *= g; v.w *= g;
        __stcs(dst + t + i * 256, v);
    }
    #pragma unroll
    for (int i = 4; i < 32; i++) {
        float4 v = src[t + i * 256];
        v.x *= g; v.y *= g; v.z *= g; v.w *= g;
        __stcs(dst + t + i * 256, v);
    }
}

extern "C" void kernel_launch(void* const* d_in, const int* in_sizes, int n_in,
                              void* d_out, int out_size) {
    const float* x  = (const float*)d_in[0];
    const float* w1 = (const float*)d_in[1];
    const float* b1 = (const float*)d_in[2];
    const float* w2 = (const float*)d_in[3];
    const float* b2 = (const float*)d_in[4];
    float* out = (float*)d_out;

    // Primary: plain launch.
    max_reduce_kernel<<<BC, 256>>>((const float4*)x);

    // Secondaries: PDL (programmatic stream serialization).
    cudaLaunchAttribute attr[1];
    attr[0].id = cudaLaunchAttributeProgrammaticStreamSerialization;
    attr[0].val.programmaticStreamSerializationAllowed = 1;

    {
        cudaLaunchConfig_t cfg = {};
        cfg.gridDim = dim3(8);
        cfg.blockDim = dim3(256);
        cfg.dynamicSmemBytes = 0;
        cfg.stream = 0;
        cfg.attrs = attr;
        cfg.numAttrs = 1;
        cudaLaunchKernelEx(&cfg, mlp_gate_kernel, w1, b1, w2, b2);
    }
    {
        cudaLaunchConfig_t cfg = {};
        cfg.gridDim = dim3(2 * BC);
        cfg.blockDim = dim3(256);
        cfg.dynamicSmemBytes = 0;
        cfg.stream = 0;
        cfg.attrs = attr;
        cfg.numAttrs = 1;
        cudaLaunchKernelEx(&cfg, scale_kernel, (const float4*)x, (float4*)out);
    }
}

// round 15
// speedup vs baseline: 1.0523x; 1.0523x over previous
#include <cuda_runtime.h>
#include <math.h>

// Shapes (fixed):
//   x  : [B=8, C=128, D=4, H=128, W=128] -> 67,108,864 fp32 (256 MB)
//   w1, w2 : [C, C] row-major (w[o,c] = w[o*128 + c]); b1, b2 : [C]
// out = x * sigmoid(W2 @ relu(W1 @ max_{dhw}(x) + b1) + b2), gate per (b,c).

#define BC 1024              // B*C slices
#define SLICE4 16384         // 65536 floats / 4 per (b,c)

__device__ float d_gp[BC];       // per-(b,c) global max
__device__ float d_gate[BC];     // per-(b,c) sigmoid gate
__device__ unsigned d_count[8];  // per-batch publish counters (zero-init; consumer resets)

// ------- Kernel 1: reduce (1024 producer blocks) + MLP (8 spin-wait consumer blocks) -------
// Producers: proven 42.2us shape (__ldcs streaming reads). Publish = ONE
// red.release.gpu per block (cheap L2 atomic; no MEMBAR.GPU, no L1 flush).
// Consumers: 1 block per batch, poll with ld.acquire.gpu + nanosleep backoff,
// then lean warp-per-channel MLP. Grid=1032 fits one wave (148 SMs x 8 blocks)
// so consumers are always co-resident -> no deadlock.
__global__ __launch_bounds__(256) void reduce_mlp_kernel(const float4* __restrict__ x4,
                                                         const float* __restrict__ w1,
                                                         const float* __restrict__ b1,
                                                         const float* __restrict__ w2,
                                                         const float* __restrict__ b2) {
    const int t = threadIdx.x;

    if (blockIdx.x < BC) {
        // ---------------- producer: per-slice max reduce ----------------
        const int bc = blockIdx.x;
        const int b = bc >> 7;
        const float4* base = x4 + (size_t)bc * SLICE4;

        float m0 = -INFINITY, m1 = -INFINITY, m2 = -INFINITY, m3 = -INFINITY;
        #pragma unroll
        for (int i = 0; i < 16; i++) {
            float4 a = __ldcs(base + t + (4 * i + 0) * 256);
            float4 bb = __ldcs(base + t + (4 * i + 1) * 256);
            float4 c = __ldcs(base + t + (4 * i + 2) * 256);
            float4 d = __ldcs(base + t + (4 * i + 3) * 256);
            m0 = fmaxf(m0, fmaxf(fmaxf(a.x, a.y), fmaxf(a.z, a.w)));
            m1 = fmaxf(m1, fmaxf(fmaxf(bb.x, bb.y), fmaxf(bb.z, bb.w)));
            m2 = fmaxf(m2, fmaxf(fmaxf(c.x, c.y), fmaxf(c.z, c.w)));
            m3 = fmaxf(m3, fmaxf(fmaxf(d.x, d.y), fmaxf(d.z, d.w)));
        }
        float m = fmaxf(fmaxf(m0, m1), fmaxf(m2, m3));

        #pragma unroll
        for (int off = 16; off > 0; off >>= 1)
            m = fmaxf(m, __shfl_xor_sync(0xFFFFFFFFu, m, off));

        __shared__ float s[8];
        if ((t & 31) == 0) s[t >> 5] = m;
        __syncthreads();
        if (t == 0) {
            float r = s[0];
            #pragma unroll
            for (int w = 1; w < 8; w++) r = fmaxf(r, s[w]);
            d_gp[bc] = r;                    // plain store (write-through to L2)
            // release-atomic publish: orders the d_gp store, no fence/L1 flush
            asm volatile("red.release.gpu.global.add.u32 [%0], %1;"
                         :: "l"(&d_count[b]), "r"(1u) : "memory");
        }
        return;
    }

    // ---------------- consumer: one block per batch, spin then MLP ----------------
    const int b = blockIdx.x - BC;
    const int wid = t >> 5, lane = t & 31;

    if (t == 0) {
        unsigned v = 0;
        do {
            asm volatile("ld.acquire.gpu.global.u32 %0, [%1];"
                         : "=r"(v) : "l"(&d_count[b]) : "memory");
            if (v < 128u) __nanosleep(200);
        } while (v < 128u);
        d_count[b] = 0;   // reset for next graph replay (all producers of b done)
    }
    __syncthreads();      // orders the acquire before everyone's d_gp reads

    __shared__ float s_gp[128];
    __shared__ float s_h[128];
    if (t < 128) s_gp[t] = d_gp[b * 128 + t];   // first touch -> L1 miss -> L2 (current)
    __syncthreads();

    // layer 1: warp w -> channels w*16..w*16+15; one float4/lane spans the row
    {
        float4 gv = ((const float4*)s_gp)[lane];
        #pragma unroll
        for (int k = 0; k < 16; k++) {
            const int c = wid * 16 + k;
            float4 wv = ((const float4*)(w1 + c * 128))[lane];
            float p = fmaf(gv.x, wv.x, fmaf(gv.y, wv.y, fmaf(gv.z, wv.z, gv.w * wv.w)));
            #pragma unroll
            for (int off = 16; off > 0; off >>= 1)
                p += __shfl_xor_sync(0xFFFFFFFFu, p, off);
            if (lane == 0) s_h[c] = fmaxf(p + b1[c], 0.0f);
        }
    }
    __syncthreads();

    // layer 2
    {
        float4 hv = ((const float4*)s_h)[lane];
        #pragma unroll
        for (int k = 0; k < 16; k++) {
            const int c = wid * 16 + k;
            float4 wv = ((const float4*)(w2 + c * 128))[lane];
            float p = fmaf(hv.x, wv.x, fmaf(hv.y, wv.y, fmaf(hv.z, wv.z, hv.w * wv.w)));
            #pragma unroll
            for (int off = 16; off > 0; off >>= 1)
                p += __shfl_xor_sync(0xFFFFFFFFu, p, off);
            if (lane == 0) {
                float z = p + b2[c];
                d_gate[b * 128 + c] = 1.0f / (1.0f + __expf(-z));
            }
        }
    }
}

// ---------------- Kernel 2: broadcast scale (measured best: 77.7us) ----------------
// Grid=2048 (2 blocks/slice), reverse order, default loads, evict-first stores.
__global__ __launch_bounds__(256) void scale_kernel(const float4* __restrict__ x4,
                                                    float4* __restrict__ o4) {
    const int blk = (2 * BC - 1) - blockIdx.x;
    const int bc = blk >> 1;
    const float g = d_gate[bc];
    const size_t off = (size_t)blk * (SLICE4 / 2);
    const float4* src = x4 + off;
    float4* dst = o4 + off;
    const int t = threadIdx.x;

    #pragma unroll
    for (int i = 0; i < 32; i++) {
        float4 v = src[t + i * 256];
        v.x *= g; v.y *= g; v.z *= g; v.w *= g;
        __stcs(dst + t + i * 256, v);
    }
}

extern "C" void kernel_launch(void* const* d_in, const int* in_sizes, int n_in,
                              void* d_out, int out_size) {
    const float* x  = (const float*)d_in[0];
    const float* w1 = (const float*)d_in[1];
    const float* b1 = (const float*)d_in[2];
    const float* w2 = (const float*)d_in[3];
    const float* b2 = (const float*)d_in[4];
    float* out = (float*)d_out;

    reduce_mlp_kernel<<<BC + 8, 256>>>((const float4*)x, w1, b1, w2, b2);
    scale_kernel<<<2 * BC, 256>>>((const float4*)x, (float4*)out);
}